// round 5
// baseline (speedup 1.0000x reference)
#include <cuda_runtime.h>
#include <cuda_bf16.h>

// Problem constants: N=64, C=4, LPC=8, KPL=4, D=4096
// BLOCK = 128, P = 384, G = LPC*KPL = 32 gaussians per (n,c) pair.
#define NN      64
#define CC      4
#define DD      4096
#define G       32
#define PP      384
#define THREADS 256
#define VEC     4
// elements per block = THREADS*VEC = 1024 ; grid = 256 nc-pairs * 4 tiles = 1024

__device__ __forceinline__ float ex2_approx(float v) {
    float r;
    asm("ex2.approx.ftz.f32 %0, %1;" : "=f"(r) : "f"(v));
    return r;
}
__device__ __forceinline__ float lg2_approx(float v) {
    float r;
    asm("lg2.approx.ftz.f32 %0, %1;" : "=f"(r) : "f"(v));
    return r;
}

__global__ __launch_bounds__(THREADS)
void GaussianSuperposition_kernel(const float* __restrict__ x,
                                  const float* __restrict__ net,
                                  const int*   __restrict__ amp_idx,
                                  const int*   __restrict__ mu_idx,
                                  const int*   __restrict__ sigma_idx,
                                  float*       __restrict__ out) {
    // Packed per-gaussian coefficients (b, p, q) with log2(e) AND log2(amp) folded:
    //   amp * exp(-0.5*(x-mu)^2/sg^2) == 2^((b*x + p)*x + q)
    __shared__ float4 s_c[G];

    const int blk  = blockIdx.x;        // 0..1023
    const int nc   = blk >> 2;          // 0..255  (n*C + c)
    const int tile = blk & 3;           // 0..3
    const int n    = nc >> 2;
    const int c    = nc & 3;
    const int t    = threadIdx.x;

    // x load issued first: its DRAM latency overlaps the coefficient gather +
    // __syncthreads below.
    const int off = nc * DD + tile * (THREADS * VEC) + t * VEC;
    const float4 xv = *reinterpret_cast<const float4*>(x + off);

    if (t < G) {
        const int gi = c * G + t;
        const float* row = net + n * PP;
        const float amp = row[amp_idx[gi]];
        const float mu  = row[mu_idx[gi]];
        const float sg  = row[sigma_idx[gi]];
        // b = -0.5*log2(e)/sg^2 ; p = -2*b*mu ; q = b*mu^2 + log2(amp)
        const float b = -0.72134752044448170f / (sg * sg);
        float4 cv;
        cv.x = b;
        cv.y = -2.0f * b * mu;
        cv.z = fmaf(b * mu, mu, lg2_approx(amp));
        cv.w = 0.0f;
        s_c[t] = cv;
    }
    __syncthreads();

    float a0 = 0.f, a1 = 0.f, a2 = 0.f, a3 = 0.f;

#pragma unroll
    for (int j = 0; j < G; ++j) {
        const float4 cv = s_c[j];
        const float b = cv.x, p = cv.y, q = cv.z;

        const float e0 = fmaf(fmaf(b, xv.x, p), xv.x, q);
        const float e1 = fmaf(fmaf(b, xv.y, p), xv.y, q);
        const float e2 = fmaf(fmaf(b, xv.z, p), xv.z, q);
        const float e3 = fmaf(fmaf(b, xv.w, p), xv.w, q);

        a0 += ex2_approx(e0);
        a1 += ex2_approx(e1);
        a2 += ex2_approx(e2);
        a3 += ex2_approx(e3);
    }

    float4 ov;
    ov.x = a0; ov.y = a1; ov.z = a2; ov.w = a3;
    *reinterpret_cast<float4*>(out + off) = ov;
}

extern "C" void kernel_launch(void* const* d_in, const int* in_sizes, int n_in,
                              void* d_out, int out_size) {
    // Defensive input binding by element count (x: 1,048,576 f32; net: 24,576 f32;
    // three 128-element i32 index arrays in order: amp, mu, sigma).
    const float* x   = nullptr;
    const float* net = nullptr;
    const int*   idx[3] = {nullptr, nullptr, nullptr};
    int nidx = 0;
    for (int i = 0; i < n_in; ++i) {
        const int sz = in_sizes[i];
        if (sz == NN * CC * DD)      x   = (const float*)d_in[i];
        else if (sz == NN * PP)      net = (const float*)d_in[i];
        else if (sz == CC * G && nidx < 3) idx[nidx++] = (const int*)d_in[i];
    }
    if (!x || !net || nidx != 3) return;

    float* out = (float*)d_out;
    GaussianSuperposition_kernel<<<NN * CC * 4, THREADS>>>(x, net, idx[0], idx[1], idx[2], out);
}